// round 11
// baseline (speedup 1.0000x reference)
#include <cuda_runtime.h>

#define BATCH 8
#define HH 2048
#define WW 2048
#define DD 16
#define FEAT 256
#define NPIX (128 * 128)

typedef unsigned long long ull;
typedef unsigned int uint;

// ---------------- device scratch ----------------
__device__ float g_tc[256];
__device__ float g_ts[256];
__device__ float g_R[DD][FEAT];
__device__ float g_I[DD][FEAT];
__device__ float g_Mt[DD * FEAT];    // M^T [n][f], FULL fp32 precision
__device__ float g_c[DD];
__device__ float g_Bhi[4096];        // B fragments (tf32 hi), lane-packed
__device__ float g_Blo[4096];        // B fragments (tf32 lo), lane-packed
__device__ float g_img[BATCH * DD * NPIX];   // 8 MB [b][d][i][j]
__device__ float g_ps[512];
__device__ float g_pq[512];
__device__ int g_cnt[DD];

// ---------------- helpers ----------------
__device__ __forceinline__ uint tf32r(float a) {
    uint u; asm("cvt.rna.tf32.f32 %0, %1;" : "=r"(u) : "f"(a)); return u;
}
__device__ __forceinline__ void cpasync8(uint saddr, const void* gaddr) {
    asm volatile("cp.async.ca.shared.global [%0], [%1], 8;" :: "r"(saddr), "l"(gaddr));
}
__device__ __forceinline__ void cpasync16(uint saddr, const void* gaddr) {
    asm volatile("cp.async.cg.shared.global [%0], [%1], 16;" :: "r"(saddr), "l"(gaddr));
}
__device__ __forceinline__ int ld_acq(const int* p) {
    int v; asm volatile("ld.acquire.gpu.b32 %0, [%1];" : "=r"(v) : "l"(p)); return v;
}
__device__ __forceinline__ void mma_tf32(float* c, const uint* a, uint b0, uint b1) {
    asm volatile(
        "mma.sync.aligned.m16n8k8.row.col.f32.tf32.tf32.f32 "
        "{%0,%1,%2,%3}, {%4,%5,%6,%7}, {%8,%9}, {%0,%1,%2,%3};"
        : "+f"(c[0]), "+f"(c[1]), "+f"(c[2]), "+f"(c[3])
        : "r"(a[0]), "r"(a[1]), "r"(a[2]), "r"(a[3]), "r"(b0), "r"(b1));
}

// ---------------- K1: table + R[j,f], I[j,f] ----------------
__global__ void k_prep1(const float* __restrict__ Wr, const float* __restrict__ Wi) {
    __shared__ float sc[256], ss[256], wr[256], wi[256];
    int f = threadIdx.x, j = blockIdx.x;
    float s, c;
    sincospif((float)f * (1.0f / 128.0f), &s, &c);
    sc[f] = c; ss[f] = s;
    if (j == 0) { g_tc[f] = c; g_ts[f] = s; }
    wr[f] = Wr[j * FEAT + f]; wi[f] = Wi[j * FEAT + f];
    __syncthreads();
    float R = 0.f, I = 0.f;
    for (int d = 0; d < 256; ++d) {
        int t = (d * f) & 255;
        float cc = sc[t], s2 = ss[t];
        R += wr[d] * cc + wi[d] * s2;
        I += wi[d] * cc - wr[d] * s2;
    }
    g_R[j][f] = R; g_I[j][f] = I;
}

// ---------------- K2: M^T (full fp32), c[k]; reset counters ----------------
__global__ void k_prep2(const float* __restrict__ br, const float* __restrict__ bi) {
    int e = blockIdx.x * 256 + threadIdx.x;
    int f = e >> 4, k = e & 15;
    float m = 0.f;
    for (int j = 0; j < DD; ++j) {
        int t = (16 * j * k) & 255;
        m += g_R[j][f] * g_tc[t] - g_I[j][f] * g_ts[t];
    }
    g_Mt[k * FEAT + f] = m * (1.0f / 16.0f);
    if (e < DD) {
        float cc = 0.f;
        for (int j = 0; j < DD; ++j) {
            int t = (16 * j * e) & 255;
            cc += (br[j] - bi[j]) * g_tc[t] - (br[j] + bi[j]) * g_ts[t];
        }
        g_c[e] = cc * (1.0f / 16.0f);
        g_cnt[e] = 0;
    }
}

// ---------------- K3: pack B fragments (lane order for m16n8k8) ----------------
// idx = ((ks*2+nt)*32 + lane)*2 + j ; b_j = B[k][n] with k = ks*8+(lane&3)+j*4,
// n = nt*8+(lane>>2); B[k][n] = Mt[n][k]. Split into tf32 hi/lo.
__global__ void k_prep3() {
    int idx = blockIdx.x * 256 + threadIdx.x;   // 4096
    int j = idx & 1;
    int lane = (idx >> 1) & 31;
    int nt = (idx >> 6) & 1;
    int ks = idx >> 7;
    int k = ks * 8 + (lane & 3) + j * 4;
    int n = nt * 8 + (lane >> 2);
    float v = g_Mt[n * FEAT + k];
    uint hb = tf32r(v);
    float hi = __uint_as_float(hb);
    uint lb = tf32r(v - hi);
    g_Bhi[idx] = hi;
    g_Blo[idx] = __uint_as_float(lb);
}

// ---------------- K4: tensor-core patch GEMM (mma.sync tf32, compensated) -----
// Block = one (b, ph): A[128x256] staged row-by-row via cp.async (3-buf ring,
// stride-20 patch rows -> conflict-free fragment LDS). Warp w: patches
// w*32..w*32+31 (2 m16 tiles) x 16 n (2 n8 tiles). 3-term tf32 compensation.
#define AROW 2560            // floats per A buffer (128 patches x 20)
#define SB_BHI (3 * AROW)    // float offsets in dynamic smem
#define SB_BLO (SB_BHI + 4096)
#define SMEM_FLOATS (SB_BLO + 4096)

__global__ void __launch_bounds__(128) k_mma(const float* __restrict__ x) {
    extern __shared__ float shm[];
    uint sb = (uint)__cvta_generic_to_shared(shm);
    int tid = threadIdx.x, w = tid >> 5, lane = tid & 31;
    int r = lane >> 2, pr = lane & 3;
    int blk = blockIdx.x;
    int b = blk >> 7, ph = blk & 127;

    const char* xbase = (const char*)(x + ((size_t)b * HH + (size_t)ph * 16) * WW);

    // stage B (16KB hi + 16KB lo) + A row 0 -> group 0
#pragma unroll
    for (int i = 0; i < 8; ++i) {
        int cid = tid + i * 128;
        cpasync16(sb + (uint)(SB_BHI * 4) + (uint)cid * 16, (const char*)g_Bhi + cid * 16);
        cpasync16(sb + (uint)(SB_BLO * 4) + (uint)cid * 16, (const char*)g_Blo + cid * 16);
    }
#pragma unroll
    for (int st = 0; st < 3; ++st) {   // rows 0..2 -> groups 0..2
        const char* src = xbase + (size_t)st * (WW * 4);
        uint dbase = sb + (uint)(st * AROW) * 4;
#pragma unroll
        for (int i = 0; i < 8; ++i) {
            int cid = tid + i * 128;           // 8B chunk id, 0..1023
            int p = cid >> 3, c2 = cid & 7;
            cpasync8(dbase + (uint)(p * 80 + c2 * 8), src + (size_t)cid * 8);
        }
        asm volatile("cp.async.commit_group;");
    }

    float acc[2][2][4];
#pragma unroll
    for (int mt = 0; mt < 2; ++mt)
#pragma unroll
        for (int nt = 0; nt < 2; ++nt)
#pragma unroll
            for (int i = 0; i < 4; ++i) acc[mt][nt][i] = 0.f;

#pragma unroll 1
    for (int s1 = 0; s1 < 16; ++s1) {
        asm volatile("cp.async.wait_group 2;");
        __syncthreads();
        const float* Ab = shm + (s1 % 3) * AROW;
#pragma unroll
        for (int kh = 0; kh < 2; ++kh) {
            int ksg = s1 * 2 + kh;
            const float2* BH = (const float2*)(shm + SB_BHI);
            const float2* BL = (const float2*)(shm + SB_BLO);
            float2 bh0 = BH[(ksg * 2 + 0) * 32 + lane];
            float2 bh1 = BH[(ksg * 2 + 1) * 32 + lane];
            float2 bl0 = BL[(ksg * 2 + 0) * 32 + lane];
            float2 bl1 = BL[(ksg * 2 + 1) * 32 + lane];
            uint bh0x = __float_as_uint(bh0.x), bh0y = __float_as_uint(bh0.y);
            uint bh1x = __float_as_uint(bh1.x), bh1y = __float_as_uint(bh1.y);
            uint bl0x = __float_as_uint(bl0.x), bl0y = __float_as_uint(bl0.y);
            uint bl1x = __float_as_uint(bl1.x), bl1y = __float_as_uint(bl1.y);
#pragma unroll
            for (int mt = 0; mt < 2; ++mt) {
                int base = (w * 32 + mt * 16 + r) * 20 + kh * 8 + pr;
                float a0 = Ab[base], a2 = Ab[base + 4];
                float a1 = Ab[base + 160], a3 = Ab[base + 164];
                uint ah[4], al[4];
                ah[0] = tf32r(a0); al[0] = tf32r(a0 - __uint_as_float(ah[0]));
                ah[1] = tf32r(a1); al[1] = tf32r(a1 - __uint_as_float(ah[1]));
                ah[2] = tf32r(a2); al[2] = tf32r(a2 - __uint_as_float(ah[2]));
                ah[3] = tf32r(a3); al[3] = tf32r(a3 - __uint_as_float(ah[3]));
                mma_tf32(acc[mt][0], ah, bh0x, bh0y);
                mma_tf32(acc[mt][0], al, bh0x, bh0y);
                mma_tf32(acc[mt][0], ah, bl0x, bl0y);
                mma_tf32(acc[mt][1], ah, bh1x, bh1y);
                mma_tf32(acc[mt][1], al, bh1x, bh1y);
                mma_tf32(acc[mt][1], ah, bl1x, bl1y);
            }
        }
        __syncthreads();
        if (s1 < 13) {   // stage row s1+3 into buffer s1%3
            const char* src = xbase + (size_t)(s1 + 3) * (WW * 4);
            uint dbase = sb + (uint)((s1 % 3) * AROW) * 4;
#pragma unroll
            for (int i = 0; i < 8; ++i) {
                int cid = tid + i * 128;
                int p = cid >> 3, c2 = cid & 7;
                cpasync8(dbase + (uint)(p * 80 + c2 * 8), src + (size_t)cid * 8);
            }
        }
        asm volatile("cp.async.commit_group;");
    }

    // epilogue: add c[n], scatter to g_img [b][n][ph*128 + p]
    float cn[2][2];   // [nt][j] for n = nt*8 + pr*2 + j
#pragma unroll
    for (int nt = 0; nt < 2; ++nt)
#pragma unroll
        for (int j = 0; j < 2; ++j) cn[nt][j] = g_c[nt * 8 + pr * 2 + j];

    float* gb = g_img + (size_t)b * DD * NPIX + ph * 128;
#pragma unroll
    for (int mt = 0; mt < 2; ++mt) {
        int p0 = w * 32 + mt * 16 + r;
#pragma unroll
        for (int nt = 0; nt < 2; ++nt) {
            int n0 = nt * 8 + pr * 2;
            gb[(size_t)n0 * NPIX + p0] = acc[mt][nt][0] + cn[nt][0];
            gb[(size_t)(n0 + 1) * NPIX + p0] = acc[mt][nt][1] + cn[nt][1];
            gb[(size_t)n0 * NPIX + p0 + 8] = acc[mt][nt][2] + cn[nt][0];
            gb[(size_t)(n0 + 1) * NPIX + p0 + 8] = acc[mt][nt][3] + cn[nt][1];
        }
    }
}

// ---------------- float4 + shfl rolling 3x3 conv ----------------
__device__ __forceinline__ void conv_rows(float4 v, int lane, const float* w,
                                          float4& h0, float4& h1, float4& h2) {
    float l = __shfl_up_sync(0xffffffffu, v.w, 1);
    float rr = __shfl_down_sync(0xffffffffu, v.x, 1);
    if (lane == 0) l = 0.f;
    if (lane == 31) rr = 0.f;
    float lx = l, ly = v.x, lz = v.y, lw = v.z;
    float rx = v.y, ry = v.z, rz = v.w, rw = rr;
#define HROW(H, W0, W1, W2)                                   \
    H.x = W0 * lx + W1 * v.x + W2 * rx;                       \
    H.y = W0 * ly + W1 * v.y + W2 * ry;                       \
    H.z = W0 * lz + W1 * v.z + W2 * rz;                       \
    H.w = W0 * lw + W1 * v.w + W2 * rw;
    HROW(h0, w[0], w[1], w[2])
    HROW(h1, w[3], w[4], w[5])
    HROW(h2, w[6], w[7], w[8])
#undef HROW
}

__device__ __forceinline__ float4 ld_row(const float* __restrict__ base, int r, int lane) {
    if ((unsigned)r < 128u) return ((const float4*)(base + r * 128))[lane];
    return make_float4(0.f, 0.f, 0.f, 0.f);
}

// ---------------- K5: fused conv + stats + grid-sync + BN + write -------------
__global__ void __launch_bounds__(256) k_fused(const float* __restrict__ cw,
                                               const float* __restrict__ cb,
                                               const float* __restrict__ gamma,
                                               const float* __restrict__ beta,
                                               float* __restrict__ out) {
    int blk = blockIdx.x;            // bd*4 + slice
    int bd = blk >> 2;
    int d = bd & 15;
    int slice = blk & 3;
    int tid = threadIdx.x;
    int lane = tid & 31, wp = tid >> 5;
    int r0 = slice * 32 + wp * 4;
    float w[9];
#pragma unroll
    for (int t = 0; t < 9; ++t) w[t] = cw[d * 9 + t];
    float bias = cb[d];
    const float* base = g_img + (size_t)bd * NPIX;

    float4 A = make_float4(0, 0, 0, 0), B = make_float4(0, 0, 0, 0);
    float4 cv[4];
    float s = 0.f, sq = 0.f;
#pragma unroll
    for (int r = r0 - 1; r <= r0 + 4; ++r) {
        float4 v = ld_row(base, r, lane);
        float4 h0, h1, h2;
        conv_rows(v, lane, w, h0, h1, h2);
        if (r >= r0 + 1) {
            float4 o;
            o.x = A.x + h2.x + bias;
            o.y = A.y + h2.y + bias;
            o.z = A.z + h2.z + bias;
            o.w = A.w + h2.w + bias;
            cv[r - 1 - r0] = o;
            s += o.x + o.y + o.z + o.w;
            sq += o.x * o.x + o.y * o.y + o.z * o.z + o.w * o.w;
        }
        A.x = B.x + h1.x; A.y = B.y + h1.y; A.z = B.z + h1.z; A.w = B.w + h1.w;
        B = h0;
    }
#pragma unroll
    for (int off = 16; off; off >>= 1) {
        s += __shfl_down_sync(0xffffffffu, s, off);
        sq += __shfl_down_sync(0xffffffffu, sq, off);
    }
    __shared__ float rs[8], rq[8];
    if (lane == 0) { rs[wp] = s; rq[wp] = sq; }
    __syncthreads();
    if (tid == 0) {
        float ts = 0.f, tq = 0.f;
#pragma unroll
        for (int i = 0; i < 8; ++i) { ts += rs[i]; tq += rq[i]; }
        g_ps[blk] = ts;
        g_pq[blk] = tq;
        __threadfence();
        atomicAdd(&g_cnt[d], 1);
        while (ld_acq(&g_cnt[d]) < 32) {}
    }
    __syncthreads();

    __shared__ float sp[32], sq2[32];
    __shared__ float smu, ssc;
    if (tid < 32) {
        int bb = tid >> 2, sl = tid & 3;
        int idx = ((bb * DD + d) << 2) + sl;
        sp[tid] = __ldcg(&g_ps[idx]);
        sq2[tid] = __ldcg(&g_pq[idx]);
        __syncwarp();
        if (tid == 0) {
            float S = 0.f, Q = 0.f;
#pragma unroll
            for (int i = 0; i < 32; ++i) { S += sp[i]; Q += sq2[i]; }
            float n = 131072.0f;
            float mu = S / n;
            float var = Q / n - mu * mu;
            smu = mu;
            ssc = rsqrtf(var + 1e-5f) * gamma[d];
        }
    }
    __syncthreads();
    float mu = smu, sc = ssc, bt = beta[d];

    float4* op = (float4*)(out + (size_t)bd * NPIX) + lane;
#pragma unroll
    for (int ri = 0; ri < 4; ++ri) {
        float4 o;
        o.x = (cv[ri].x - mu) * sc + bt;
        o.y = (cv[ri].y - mu) * sc + bt;
        o.z = (cv[ri].z - mu) * sc + bt;
        o.w = (cv[ri].w - mu) * sc + bt;
        op[(r0 + ri) * 32] = o;
    }
}

extern "C" void kernel_launch(void* const* d_in, const int* in_sizes, int n_in,
                              void* d_out, int out_size) {
    const float* x = (const float*)d_in[0];
    const float* Wr = (const float*)d_in[1];
    const float* br = (const float*)d_in[2];
    const float* Wi = (const float*)d_in[3];
    const float* bi = (const float*)d_in[4];
    const float* cw = (const float*)d_in[5];
    const float* cb = (const float*)d_in[6];
    const float* gamma = (const float*)d_in[7];
    const float* beta = (const float*)d_in[8];
    float* out = (float*)d_out;

    static int smem_set = 0;
    if (!smem_set) {
        cudaFuncSetAttribute(k_mma, cudaFuncAttributeMaxDynamicSharedMemorySize,
                             SMEM_FLOATS * 4);
        smem_set = 1;
    }

    k_prep1<<<16, 256>>>(Wr, Wi);
    k_prep2<<<16, 256>>>(br, bi);
    k_prep3<<<16, 256>>>();
    k_mma<<<1024, 128, SMEM_FLOATS * 4>>>(x);
    k_fused<<<512, 256>>>(cw, cb, gamma, beta, out);
}

// round 12
// speedup vs baseline: 1.0092x; 1.0092x over previous
#include <cuda_runtime.h>

#define BATCH 8
#define HH 2048
#define WW 2048
#define DD 16
#define FEAT 256
#define NPIX (128 * 128)

typedef unsigned long long ull;
typedef unsigned int uint;

// ---------------- device scratch ----------------
__device__ float g_tc[256];
__device__ float g_ts[256];
__device__ float g_R[DD][FEAT];
__device__ float g_I[DD][FEAT];
__device__ float g_Mt[DD * FEAT];    // M^T [n][f], FULL fp32 precision
__device__ float g_c[DD];
__device__ float g_Bhi[4096];        // B fragments (tf32 hi), lane-packed
__device__ float g_Blo[4096];        // B fragments (tf32 lo), lane-packed
__device__ float g_img[BATCH * DD * NPIX];   // 8 MB [b][d][i][j]
__device__ float g_ps[512];
__device__ float g_pq[512];
__device__ int g_cnt[DD];

// ---------------- helpers ----------------
__device__ __forceinline__ uint tf32r(float a) {
    uint u; asm("cvt.rna.tf32.f32 %0, %1;" : "=r"(u) : "f"(a)); return u;
}
__device__ __forceinline__ void cpasync16(uint saddr, const void* gaddr) {
    asm volatile("cp.async.cg.shared.global [%0], [%1], 16;" :: "r"(saddr), "l"(gaddr));
}
__device__ __forceinline__ int ld_acq(const int* p) {
    int v; asm volatile("ld.acquire.gpu.b32 %0, [%1];" : "=r"(v) : "l"(p)); return v;
}
__device__ __forceinline__ void mma_tf32(float* c, const uint* a, uint b0, uint b1) {
    asm volatile(
        "mma.sync.aligned.m16n8k8.row.col.f32.tf32.tf32.f32 "
        "{%0,%1,%2,%3}, {%4,%5,%6,%7}, {%8,%9}, {%0,%1,%2,%3};"
        : "+f"(c[0]), "+f"(c[1]), "+f"(c[2]), "+f"(c[3])
        : "r"(a[0]), "r"(a[1]), "r"(a[2]), "r"(a[3]), "r"(b0), "r"(b1));
}

// ---------------- K1: table + R[j,f], I[j,f] ----------------
__global__ void k_prep1(const float* __restrict__ Wr, const float* __restrict__ Wi) {
    __shared__ float sc[256], ss[256], wr[256], wi[256];
    int f = threadIdx.x, j = blockIdx.x;
    float s, c;
    sincospif((float)f * (1.0f / 128.0f), &s, &c);
    sc[f] = c; ss[f] = s;
    if (j == 0) { g_tc[f] = c; g_ts[f] = s; }
    wr[f] = Wr[j * FEAT + f]; wi[f] = Wi[j * FEAT + f];
    __syncthreads();
    float R = 0.f, I = 0.f;
    for (int d = 0; d < 256; ++d) {
        int t = (d * f) & 255;
        float cc = sc[t], s2 = ss[t];
        R += wr[d] * cc + wi[d] * s2;
        I += wi[d] * cc - wr[d] * s2;
    }
    g_R[j][f] = R; g_I[j][f] = I;
}

// ---------------- K2: M^T (full fp32), c[k]; reset counters ----------------
__global__ void k_prep2(const float* __restrict__ br, const float* __restrict__ bi) {
    int e = blockIdx.x * 256 + threadIdx.x;
    int f = e >> 4, k = e & 15;
    float m = 0.f;
    for (int j = 0; j < DD; ++j) {
        int t = (16 * j * k) & 255;
        m += g_R[j][f] * g_tc[t] - g_I[j][f] * g_ts[t];
    }
    g_Mt[k * FEAT + f] = m * (1.0f / 16.0f);
    if (e < DD) {
        float cc = 0.f;
        for (int j = 0; j < DD; ++j) {
            int t = (16 * j * e) & 255;
            cc += (br[j] - bi[j]) * g_tc[t] - (br[j] + bi[j]) * g_ts[t];
        }
        g_c[e] = cc * (1.0f / 16.0f);
        g_cnt[e] = 0;
    }
}

// ---------------- K3: pack B fragments (lane order for m16n8k8) ----------------
__global__ void k_prep3() {
    int idx = blockIdx.x * 256 + threadIdx.x;   // 4096
    int j = idx & 1;
    int lane = (idx >> 1) & 31;
    int nt = (idx >> 6) & 1;
    int ks = idx >> 7;
    int k = ks * 8 + (lane & 3) + j * 4;
    int n = nt * 8 + (lane >> 2);
    float v = g_Mt[n * FEAT + k];
    uint hb = tf32r(v);
    float hi = __uint_as_float(hb);
    uint lb = tf32r(v - hi);
    g_Bhi[idx] = hi;
    g_Blo[idx] = __uint_as_float(lb);
}

// ---------------- K4: tensor-core patch GEMM (mma.sync tf32, compensated) -----
// Block = one (b, ph): A[128x256] staged row-by-row via cp.async, 2-buf ring,
// stride-20 patch rows (80B = 16B-aligned, conflict-free fragment LDS).
// Warp w: patches w*32..w*32+31 (2 m16 tiles) x 16 n (2 n8 tiles).
// 3-term tf32 compensation: ah*bh + al*bh + ah*bl.
#define AROW 2560            // floats per A buffer (128 patches x 20)
#define SB_BHI (2 * AROW)    // float offsets in dynamic smem
#define SB_BLO (SB_BHI + 4096)
#define SMEM_FLOATS (SB_BLO + 4096)

__global__ void __launch_bounds__(128) k_mma(const float* __restrict__ x) {
    extern __shared__ float shm[];
    uint sb = (uint)__cvta_generic_to_shared(shm);
    int tid = threadIdx.x, w = tid >> 5, lane = tid & 31;
    int r = lane >> 2, pr = lane & 3;
    int blk = blockIdx.x;
    int b = blk >> 7, ph = blk & 127;

    const char* xbase = (const char*)(x + ((size_t)b * HH + (size_t)ph * 16) * WW);

    // group 0: B (16KB hi + 16KB lo) + A row 0
#pragma unroll
    for (int i = 0; i < 8; ++i) {
        int cid = tid + i * 128;
        cpasync16(sb + (uint)(SB_BHI * 4) + (uint)cid * 16, (const char*)g_Bhi + cid * 16);
        cpasync16(sb + (uint)(SB_BLO * 4) + (uint)cid * 16, (const char*)g_Blo + cid * 16);
    }
    {
        uint dbase = sb;
#pragma unroll
        for (int i = 0; i < 4; ++i) {
            int cid = tid + i * 128;           // 16B chunk id, 0..511
            int p = cid >> 2, c4 = cid & 3;
            cpasync16(dbase + (uint)(p * 80 + c4 * 16), xbase + (size_t)cid * 16);
        }
        asm volatile("cp.async.commit_group;");
    }
    // group 1: A row 1
    {
        const char* src = xbase + (size_t)(WW * 4);
        uint dbase = sb + (uint)AROW * 4;
#pragma unroll
        for (int i = 0; i < 4; ++i) {
            int cid = tid + i * 128;
            int p = cid >> 2, c4 = cid & 3;
            cpasync16(dbase + (uint)(p * 80 + c4 * 16), src + (size_t)cid * 16);
        }
        asm volatile("cp.async.commit_group;");
    }

    float acc[2][2][4];
#pragma unroll
    for (int mt = 0; mt < 2; ++mt)
#pragma unroll
        for (int nt = 0; nt < 2; ++nt)
#pragma unroll
            for (int i = 0; i < 4; ++i) acc[mt][nt][i] = 0.f;

    int abase0 = (w * 32 + r) * 20 + pr;   // fragment base (floats) within buffer

#pragma unroll 1
    for (int s1 = 0; s1 < 16; ++s1) {
        asm volatile("cp.async.wait_group 1;");
        __syncthreads();
        const float* Aw = shm + (s1 & 1) * AROW + abase0;
#pragma unroll
        for (int kh = 0; kh < 2; ++kh) {
            int ksg = s1 * 2 + kh;
            const float2* BH = (const float2*)(shm + SB_BHI);
            const float2* BL = (const float2*)(shm + SB_BLO);
            float2 bh0 = BH[(ksg * 2 + 0) * 32 + lane];
            float2 bh1 = BH[(ksg * 2 + 1) * 32 + lane];
            float2 bl0 = BL[(ksg * 2 + 0) * 32 + lane];
            float2 bl1 = BL[(ksg * 2 + 1) * 32 + lane];
            uint bh0x = __float_as_uint(bh0.x), bh0y = __float_as_uint(bh0.y);
            uint bh1x = __float_as_uint(bh1.x), bh1y = __float_as_uint(bh1.y);
            uint bl0x = __float_as_uint(bl0.x), bl0y = __float_as_uint(bl0.y);
            uint bl1x = __float_as_uint(bl1.x), bl1y = __float_as_uint(bl1.y);
            const float* Ak = Aw + kh * 8;
#pragma unroll
            for (int mt = 0; mt < 2; ++mt) {
                const float* Am = Ak + mt * 320;   // 16 patches * 20 floats
                float a0 = Am[0], a2 = Am[4];
                float a1 = Am[160], a3 = Am[164];
                uint ah[4], al[4];
                ah[0] = tf32r(a0); al[0] = tf32r(a0 - __uint_as_float(ah[0]));
                ah[1] = tf32r(a1); al[1] = tf32r(a1 - __uint_as_float(ah[1]));
                ah[2] = tf32r(a2); al[2] = tf32r(a2 - __uint_as_float(ah[2]));
                ah[3] = tf32r(a3); al[3] = tf32r(a3 - __uint_as_float(ah[3]));
                mma_tf32(acc[mt][0], ah, bh0x, bh0y);
                mma_tf32(acc[mt][0], al, bh0x, bh0y);
                mma_tf32(acc[mt][0], ah, bl0x, bl0y);
                mma_tf32(acc[mt][1], ah, bh1x, bh1y);
                mma_tf32(acc[mt][1], al, bh1x, bh1y);
                mma_tf32(acc[mt][1], ah, bl1x, bl1y);
            }
        }
        __syncthreads();
        if (s1 < 14) {   // stage row s1+2 into buffer (s1&1)
            const char* src = xbase + (size_t)(s1 + 2) * (WW * 4);
            uint dbase = sb + (uint)((s1 & 1) * AROW) * 4;
#pragma unroll
            for (int i = 0; i < 4; ++i) {
                int cid = tid + i * 128;
                int p = cid >> 2, c4 = cid & 3;
                cpasync16(dbase + (uint)(p * 80 + c4 * 16), src + (size_t)cid * 16);
            }
        }
        asm volatile("cp.async.commit_group;");
    }

    // epilogue: add c[n], scatter to g_img [b][n][ph*128 + p]
    float cn[2][2];
#pragma unroll
    for (int nt = 0; nt < 2; ++nt)
#pragma unroll
        for (int j = 0; j < 2; ++j) cn[nt][j] = g_c[nt * 8 + pr * 2 + j];

    float* gb = g_img + (size_t)b * DD * NPIX + ph * 128;
#pragma unroll
    for (int mt = 0; mt < 2; ++mt) {
        int p0 = w * 32 + mt * 16 + r;
#pragma unroll
        for (int nt = 0; nt < 2; ++nt) {
            int n0 = nt * 8 + pr * 2;
            gb[(size_t)n0 * NPIX + p0] = acc[mt][nt][0] + cn[nt][0];
            gb[(size_t)(n0 + 1) * NPIX + p0] = acc[mt][nt][1] + cn[nt][1];
            gb[(size_t)n0 * NPIX + p0 + 8] = acc[mt][nt][2] + cn[nt][0];
            gb[(size_t)(n0 + 1) * NPIX + p0 + 8] = acc[mt][nt][3] + cn[nt][1];
        }
    }
}

// ---------------- float4 + shfl rolling 3x3 conv ----------------
__device__ __forceinline__ void conv_rows(float4 v, int lane, const float* w,
                                          float4& h0, float4& h1, float4& h2) {
    float l = __shfl_up_sync(0xffffffffu, v.w, 1);
    float rr = __shfl_down_sync(0xffffffffu, v.x, 1);
    if (lane == 0) l = 0.f;
    if (lane == 31) rr = 0.f;
    float lx = l, ly = v.x, lz = v.y, lw = v.z;
    float rx = v.y, ry = v.z, rz = v.w, rw = rr;
#define HROW(H, W0, W1, W2)                                   \
    H.x = W0 * lx + W1 * v.x + W2 * rx;                       \
    H.y = W0 * ly + W1 * v.y + W2 * ry;                       \
    H.z = W0 * lz + W1 * v.z + W2 * rz;                       \
    H.w = W0 * lw + W1 * v.w + W2 * rw;
    HROW(h0, w[0], w[1], w[2])
    HROW(h1, w[3], w[4], w[5])
    HROW(h2, w[6], w[7], w[8])
#undef HROW
}

__device__ __forceinline__ float4 ld_row(const float* __restrict__ base, int r, int lane) {
    if ((unsigned)r < 128u) return ((const float4*)(base + r * 128))[lane];
    return make_float4(0.f, 0.f, 0.f, 0.f);
}

// ---------------- K5: fused conv + stats + grid-sync + BN + write -------------
__global__ void __launch_bounds__(256) k_fused(const float* __restrict__ cw,
                                               const float* __restrict__ cb,
                                               const float* __restrict__ gamma,
                                               const float* __restrict__ beta,
                                               float* __restrict__ out) {
    int blk = blockIdx.x;            // bd*4 + slice
    int bd = blk >> 2;
    int d = bd & 15;
    int slice = blk & 3;
    int tid = threadIdx.x;
    int lane = tid & 31, wp = tid >> 5;
    int r0 = slice * 32 + wp * 4;
    float w[9];
#pragma unroll
    for (int t = 0; t < 9; ++t) w[t] = cw[d * 9 + t];
    float bias = cb[d];
    const float* base = g_img + (size_t)bd * NPIX;

    float4 A = make_float4(0, 0, 0, 0), B = make_float4(0, 0, 0, 0);
    float4 cv[4];
    float s = 0.f, sq = 0.f;
#pragma unroll
    for (int r = r0 - 1; r <= r0 + 4; ++r) {
        float4 v = ld_row(base, r, lane);
        float4 h0, h1, h2;
        conv_rows(v, lane, w, h0, h1, h2);
        if (r >= r0 + 1) {
            float4 o;
            o.x = A.x + h2.x + bias;
            o.y = A.y + h2.y + bias;
            o.z = A.z + h2.z + bias;
            o.w = A.w + h2.w + bias;
            cv[r - 1 - r0] = o;
            s += o.x + o.y + o.z + o.w;
            sq += o.x * o.x + o.y * o.y + o.z * o.z + o.w * o.w;
        }
        A.x = B.x + h1.x; A.y = B.y + h1.y; A.z = B.z + h1.z; A.w = B.w + h1.w;
        B = h0;
    }
#pragma unroll
    for (int off = 16; off; off >>= 1) {
        s += __shfl_down_sync(0xffffffffu, s, off);
        sq += __shfl_down_sync(0xffffffffu, sq, off);
    }
    __shared__ float rs[8], rq[8];
    if (lane == 0) { rs[wp] = s; rq[wp] = sq; }
    __syncthreads();
    if (tid == 0) {
        float ts = 0.f, tq = 0.f;
#pragma unroll
        for (int i = 0; i < 8; ++i) { ts += rs[i]; tq += rq[i]; }
        g_ps[blk] = ts;
        g_pq[blk] = tq;
        __threadfence();
        atomicAdd(&g_cnt[d], 1);
        while (ld_acq(&g_cnt[d]) < 32) {}
    }
    __syncthreads();

    __shared__ float sp[32], sq2[32];
    __shared__ float smu, ssc;
    if (tid < 32) {
        int bb = tid >> 2, sl = tid & 3;
        int idx = ((bb * DD + d) << 2) + sl;
        sp[tid] = __ldcg(&g_ps[idx]);
        sq2[tid] = __ldcg(&g_pq[idx]);
        __syncwarp();
        if (tid == 0) {
            float S = 0.f, Q = 0.f;
#pragma unroll
            for (int i = 0; i < 32; ++i) { S += sp[i]; Q += sq2[i]; }
            float n = 131072.0f;
            float mu = S / n;
            float var = Q / n - mu * mu;
            smu = mu;
            ssc = rsqrtf(var + 1e-5f) * gamma[d];
        }
    }
    __syncthreads();
    float mu = smu, sc = ssc, bt = beta[d];

    float4* op = (float4*)(out + (size_t)bd * NPIX) + lane;
#pragma unroll
    for (int ri = 0; ri < 4; ++ri) {
        float4 o;
        o.x = (cv[ri].x - mu) * sc + bt;
        o.y = (cv[ri].y - mu) * sc + bt;
        o.z = (cv[ri].z - mu) * sc + bt;
        o.w = (cv[ri].w - mu) * sc + bt;
        op[(r0 + ri) * 32] = o;
    }
}

extern "C" void kernel_launch(void* const* d_in, const int* in_sizes, int n_in,
                              void* d_out, int out_size) {
    const float* x = (const float*)d_in[0];
    const float* Wr = (const float*)d_in[1];
    const float* br = (const float*)d_in[2];
    const float* Wi = (const float*)d_in[3];
    const float* bi = (const float*)d_in[4];
    const float* cw = (const float*)d_in[5];
    const float* cb = (const float*)d_in[6];
    const float* gamma = (const float*)d_in[7];
    const float* beta = (const float*)d_in[8];
    float* out = (float*)d_out;

    static int smem_set = 0;
    if (!smem_set) {
        cudaFuncSetAttribute(k_mma, cudaFuncAttributeMaxDynamicSharedMemorySize,
                             SMEM_FLOATS * 4);
        smem_set = 1;
    }

    k_prep1<<<16, 256>>>(Wr, Wi);
    k_prep2<<<16, 256>>>(br, bi);
    k_prep3<<<16, 256>>>();
    k_mma<<<1024, 128, SMEM_FLOATS * 4>>>(x);
    k_fused<<<512, 256>>>(cw, cb, gamma, beta, out);
}

// round 13
// speedup vs baseline: 1.0808x; 1.0710x over previous
#include <cuda_runtime.h>

#define BATCH 8
#define HH 2048
#define WW 2048
#define DD 16
#define FEAT 256
#define NPIX (128 * 128)

typedef unsigned long long ull;
typedef unsigned int uint;

// ---------------- device scratch ----------------
__device__ float g_tc[256];
__device__ float g_ts[256];
__device__ float g_R[DD][FEAT];
__device__ float g_I[DD][FEAT];
__device__ float g_c[DD];
__device__ float g_Bhi[4096];        // B fragments (tf32 hi), lane-packed
__device__ float g_Blo[4096];        // B fragments (tf32 lo), lane-packed
__device__ float g_img[BATCH * DD * NPIX];   // 8 MB [b][d][i][j]
__device__ float g_ps[512];
__device__ float g_pq[512];
__device__ int g_cnt[DD];

// ---------------- helpers ----------------
__device__ __forceinline__ uint tf32r(float a) {
    uint u; asm("cvt.rna.tf32.f32 %0, %1;" : "=r"(u) : "f"(a)); return u;
}
__device__ __forceinline__ void cpasync16(uint saddr, const void* gaddr) {
    asm volatile("cp.async.cg.shared.global [%0], [%1], 16;" :: "r"(saddr), "l"(gaddr));
}
__device__ __forceinline__ int ld_acq(const int* p) {
    int v; asm volatile("ld.acquire.gpu.b32 %0, [%1];" : "=r"(v) : "l"(p)); return v;
}
__device__ __forceinline__ void mma_tf32(float* c, const uint* a, uint b0, uint b1) {
    asm volatile(
        "mma.sync.aligned.m16n8k8.row.col.f32.tf32.tf32.f32 "
        "{%0,%1,%2,%3}, {%4,%5,%6,%7}, {%8,%9}, {%0,%1,%2,%3};"
        : "+f"(c[0]), "+f"(c[1]), "+f"(c[2]), "+f"(c[3])
        : "r"(a[0]), "r"(a[1]), "r"(a[2]), "r"(a[3]), "r"(b0), "r"(b1));
}

// ---------------- K1: table + R[j,f], I[j,f] ----------------
__global__ void k_prep1(const float* __restrict__ Wr, const float* __restrict__ Wi) {
    __shared__ float sc[256], ss[256], wr[256], wi[256];
    int f = threadIdx.x, j = blockIdx.x;
    float s, c;
    sincospif((float)f * (1.0f / 128.0f), &s, &c);
    sc[f] = c; ss[f] = s;
    if (j == 0) { g_tc[f] = c; g_ts[f] = s; }
    wr[f] = Wr[j * FEAT + f]; wi[f] = Wi[j * FEAT + f];
    __syncthreads();
    float R = 0.f, I = 0.f;
    for (int d = 0; d < 256; ++d) {
        int t = (d * f) & 255;
        float cc = sc[t], s2 = ss[t];
        R += wr[d] * cc + wi[d] * s2;
        I += wi[d] * cc - wr[d] * s2;
    }
    g_R[j][f] = R; g_I[j][f] = I;
}

// ---------------- K2: M^T -> B fragments directly; c[k]; reset counters ------
// Thread e computes Mt[n][f] (n = e&15, f = e>>4) and scatters its tf32 hi/lo
// straight into the m16n8k8 lane-packed fragment arrays.
__global__ void k_prep2(const float* __restrict__ br, const float* __restrict__ bi) {
    int e = blockIdx.x * 256 + threadIdx.x;
    int f = e >> 4, n = e & 15;
    float m = 0.f;
    for (int j = 0; j < DD; ++j) {
        int t = (16 * j * n) & 255;
        m += g_R[j][f] * g_tc[t] - g_I[j][f] * g_ts[t];
    }
    m *= (1.0f / 16.0f);
    uint hb = tf32r(m);
    float hi = __uint_as_float(hb);
    uint lb = tf32r(m - hi);
    int ks = f >> 3, rem = f & 7;
    int jj = rem >> 2;
    int lane = ((n & 7) << 2) | (rem & 3);
    int nt = n >> 3;
    int idx = (ks << 7) | (nt << 6) | (lane << 1) | jj;
    g_Bhi[idx] = hi;
    g_Blo[idx] = __uint_as_float(lb);
    if (e < DD) {
        float cc = 0.f;
        for (int j = 0; j < DD; ++j) {
            int t = (16 * j * e) & 255;
            cc += (br[j] - bi[j]) * g_tc[t] - (br[j] + bi[j]) * g_ts[t];
        }
        g_c[e] = cc * (1.0f / 16.0f);
        g_cnt[e] = 0;
    }
}

// ---------------- K3: tensor-core patch GEMM (mma.sync tf32, compensated) -----
// Block = one (b, ph), 256 threads / 8 warps. Warp w: m16 tile w (patches
// w*16..w*16+15) x 16 n. A staged row-by-row via cp.async 2-buf ring with
// stride-20 patch rows. 3-term tf32 compensation: ah*bh + al*bh + ah*bl.
#define AROW 2560            // floats per A buffer (128 patches x 20)
#define SB_BHI (2 * AROW)
#define SB_BLO (SB_BHI + 4096)
#define SMEM_FLOATS (SB_BLO + 4096)

__global__ void __launch_bounds__(256, 4) k_mma(const float* __restrict__ x) {
    extern __shared__ float shm[];
    uint sb = (uint)__cvta_generic_to_shared(shm);
    int tid = threadIdx.x, w = tid >> 5, lane = tid & 31;
    int r = lane >> 2, pr = lane & 3;
    int blk = blockIdx.x;
    int b = blk >> 7, ph = blk & 127;

    const char* xbase = (const char*)(x + ((size_t)b * HH + (size_t)ph * 16) * WW);

    // group 0: B (16KB hi + 16KB lo) + A row 0
#pragma unroll
    for (int i = 0; i < 4; ++i) {
        int cid = tid + i * 256;
        cpasync16(sb + (uint)(SB_BHI * 4) + (uint)cid * 16, (const char*)g_Bhi + cid * 16);
        cpasync16(sb + (uint)(SB_BLO * 4) + (uint)cid * 16, (const char*)g_Blo + cid * 16);
    }
    {
#pragma unroll
        for (int i = 0; i < 2; ++i) {
            int cid = tid + i * 256;           // 16B chunk id, 0..511
            int p = cid >> 2, c4 = cid & 3;
            cpasync16(sb + (uint)(p * 80 + c4 * 16), xbase + (size_t)cid * 16);
        }
        asm volatile("cp.async.commit_group;");
    }
    // group 1: A row 1
    {
        const char* src = xbase + (size_t)(WW * 4);
        uint dbase = sb + (uint)AROW * 4;
#pragma unroll
        for (int i = 0; i < 2; ++i) {
            int cid = tid + i * 256;
            int p = cid >> 2, c4 = cid & 3;
            cpasync16(dbase + (uint)(p * 80 + c4 * 16), src + (size_t)cid * 16);
        }
        asm volatile("cp.async.commit_group;");
    }

    float acc[2][4];
#pragma unroll
    for (int nt = 0; nt < 2; ++nt)
#pragma unroll
        for (int i = 0; i < 4; ++i) acc[nt][i] = 0.f;

    int abase0 = (w * 16 + r) * 20 + pr;      // fragment base within A buffer

#pragma unroll 1
    for (int s1 = 0; s1 < 16; ++s1) {
        asm volatile("cp.async.wait_group 1;");
        __syncthreads();
        const float* Aw = shm + (s1 & 1) * AROW + abase0;
        const float2* Bp = (const float2*)(shm + SB_BHI) + s1 * 128 + lane;
        const float2* Lp = (const float2*)(shm + SB_BLO) + s1 * 128 + lane;
#pragma unroll
        for (int kh = 0; kh < 2; ++kh) {
            float2 bh0 = Bp[kh * 64];
            float2 bh1 = Bp[kh * 64 + 32];
            float2 bl0 = Lp[kh * 64];
            float2 bl1 = Lp[kh * 64 + 32];
            uint bh0x = __float_as_uint(bh0.x), bh0y = __float_as_uint(bh0.y);
            uint bh1x = __float_as_uint(bh1.x), bh1y = __float_as_uint(bh1.y);
            uint bl0x = __float_as_uint(bl0.x), bl0y = __float_as_uint(bl0.y);
            uint bl1x = __float_as_uint(bl1.x), bl1y = __float_as_uint(bl1.y);
            const float* Ak = Aw + kh * 8;
            float a0 = Ak[0], a2 = Ak[4];
            float a1 = Ak[160], a3 = Ak[164];
            uint ah[4], al[4];
            ah[0] = tf32r(a0); al[0] = tf32r(a0 - __uint_as_float(ah[0]));
            ah[1] = tf32r(a1); al[1] = tf32r(a1 - __uint_as_float(ah[1]));
            ah[2] = tf32r(a2); al[2] = tf32r(a2 - __uint_as_float(ah[2]));
            ah[3] = tf32r(a3); al[3] = tf32r(a3 - __uint_as_float(ah[3]));
            mma_tf32(acc[0], ah, bh0x, bh0y);
            mma_tf32(acc[0], al, bh0x, bh0y);
            mma_tf32(acc[0], ah, bl0x, bl0y);
            mma_tf32(acc[1], ah, bh1x, bh1y);
            mma_tf32(acc[1], al, bh1x, bh1y);
            mma_tf32(acc[1], ah, bl1x, bl1y);
        }
        __syncthreads();
        if (s1 < 14) {   // stage row s1+2 into buffer (s1&1)
            const char* src = xbase + (size_t)(s1 + 2) * (WW * 4);
            uint dbase = sb + (uint)((s1 & 1) * AROW) * 4;
#pragma unroll
            for (int i = 0; i < 2; ++i) {
                int cid = tid + i * 256;
                int p = cid >> 2, c4 = cid & 3;
                cpasync16(dbase + (uint)(p * 80 + c4 * 16), src + (size_t)cid * 16);
            }
        }
        asm volatile("cp.async.commit_group;");
    }

    // epilogue: add c[n], scatter to g_img [b][n][ph*128 + p]
    float cn[2][2];
#pragma unroll
    for (int nt = 0; nt < 2; ++nt)
#pragma unroll
        for (int j = 0; j < 2; ++j) cn[nt][j] = g_c[nt * 8 + pr * 2 + j];

    float* gb = g_img + (size_t)b * DD * NPIX + ph * 128;
    int p0 = w * 16 + r;
#pragma unroll
    for (int nt = 0; nt < 2; ++nt) {
        int n0 = nt * 8 + pr * 2;
        gb[(size_t)n0 * NPIX + p0] = acc[nt][0] + cn[nt][0];
        gb[(size_t)(n0 + 1) * NPIX + p0] = acc[nt][1] + cn[nt][1];
        gb[(size_t)n0 * NPIX + p0 + 8] = acc[nt][2] + cn[nt][0];
        gb[(size_t)(n0 + 1) * NPIX + p0 + 8] = acc[nt][3] + cn[nt][1];
    }
}

// ---------------- float4 + shfl rolling 3x3 conv ----------------
__device__ __forceinline__ void conv_rows(float4 v, int lane, const float* w,
                                          float4& h0, float4& h1, float4& h2) {
    float l = __shfl_up_sync(0xffffffffu, v.w, 1);
    float rr = __shfl_down_sync(0xffffffffu, v.x, 1);
    if (lane == 0) l = 0.f;
    if (lane == 31) rr = 0.f;
    float lx = l, ly = v.x, lz = v.y, lw = v.z;
    float rx = v.y, ry = v.z, rz = v.w, rw = rr;
#define HROW(H, W0, W1, W2)                                   \
    H.x = W0 * lx + W1 * v.x + W2 * rx;                       \
    H.y = W0 * ly + W1 * v.y + W2 * ry;                       \
    H.z = W0 * lz + W1 * v.z + W2 * rz;                       \
    H.w = W0 * lw + W1 * v.w + W2 * rw;
    HROW(h0, w[0], w[1], w[2])
    HROW(h1, w[3], w[4], w[5])
    HROW(h2, w[6], w[7], w[8])
#undef HROW
}

__device__ __forceinline__ float4 ld_row(const float* __restrict__ base, int r, int lane) {
    if ((unsigned)r < 128u) return ((const float4*)(base + r * 128))[lane];
    return make_float4(0.f, 0.f, 0.f, 0.f);
}

// ---------------- K4: fused conv + stats + grid-sync + BN + write -------------
__global__ void __launch_bounds__(256) k_fused(const float* __restrict__ cw,
                                               const float* __restrict__ cb,
                                               const float* __restrict__ gamma,
                                               const float* __restrict__ beta,
                                               float* __restrict__ out) {
    int blk = blockIdx.x;            // bd*4 + slice
    int bd = blk >> 2;
    int d = bd & 15;
    int slice = blk & 3;
    int tid = threadIdx.x;
    int lane = tid & 31, wp = tid >> 5;
    int r0 = slice * 32 + wp * 4;
    float w[9];
#pragma unroll
    for (int t = 0; t < 9; ++t) w[t] = cw[d * 9 + t];
    float bias = cb[d];
    const float* base = g_img + (size_t)bd * NPIX;

    float4 A = make_float4(0, 0, 0, 0), B = make_float4(0, 0, 0, 0);
    float4 cv[4];
    float s = 0.f, sq = 0.f;
#pragma unroll
    for (int r = r0 - 1; r <= r0 + 4; ++r) {
        float4 v = ld_row(base, r, lane);
        float4 h0, h1, h2;
        conv_rows(v, lane, w, h0, h1, h2);
        if (r >= r0 + 1) {
            float4 o;
            o.x = A.x + h2.x + bias;
            o.y = A.y + h2.y + bias;
            o.z = A.z + h2.z + bias;
            o.w = A.w + h2.w + bias;
            cv[r - 1 - r0] = o;
            s += o.x + o.y + o.z + o.w;
            sq += o.x * o.x + o.y * o.y + o.z * o.z + o.w * o.w;
        }
        A.x = B.x + h1.x; A.y = B.y + h1.y; A.z = B.z + h1.z; A.w = B.w + h1.w;
        B = h0;
    }
#pragma unroll
    for (int off = 16; off; off >>= 1) {
        s += __shfl_down_sync(0xffffffffu, s, off);
        sq += __shfl_down_sync(0xffffffffu, sq, off);
    }
    __shared__ float rs[8], rq[8];
    if (lane == 0) { rs[wp] = s; rq[wp] = sq; }
    __syncthreads();
    if (tid == 0) {
        float ts = 0.f, tq = 0.f;
#pragma unroll
        for (int i = 0; i < 8; ++i) { ts += rs[i]; tq += rq[i]; }
        g_ps[blk] = ts;
        g_pq[blk] = tq;
        __threadfence();
        atomicAdd(&g_cnt[d], 1);
        while (ld_acq(&g_cnt[d]) < 32) {}
    }
    __syncthreads();

    __shared__ float sp[32], sq2[32];
    __shared__ float smu, ssc;
    if (tid < 32) {
        int bb = tid >> 2, sl = tid & 3;
        int idx = ((bb * DD + d) << 2) + sl;
        sp[tid] = __ldcg(&g_ps[idx]);
        sq2[tid] = __ldcg(&g_pq[idx]);
        __syncwarp();
        if (tid == 0) {
            float S = 0.f, Q = 0.f;
#pragma unroll
            for (int i = 0; i < 32; ++i) { S += sp[i]; Q += sq2[i]; }
            float n = 131072.0f;
            float mu = S / n;
            float var = Q / n - mu * mu;
            smu = mu;
            ssc = rsqrtf(var + 1e-5f) * gamma[d];
        }
    }
    __syncthreads();
    float mu = smu, sc = ssc, bt = beta[d];

    float4* op = (float4*)(out + (size_t)bd * NPIX) + lane;
#pragma unroll
    for (int ri = 0; ri < 4; ++ri) {
        float4 o;
        o.x = (cv[ri].x - mu) * sc + bt;
        o.y = (cv[ri].y - mu) * sc + bt;
        o.z = (cv[ri].z - mu) * sc + bt;
        o.w = (cv[ri].w - mu) * sc + bt;
        op[(r0 + ri) * 32] = o;
    }
}

extern "C" void kernel_launch(void* const* d_in, const int* in_sizes, int n_in,
                              void* d_out, int out_size) {
    const float* x = (const float*)d_in[0];
    const float* Wr = (const float*)d_in[1];
    const float* br = (const float*)d_in[2];
    const float* Wi = (const float*)d_in[3];
    const float* bi = (const float*)d_in[4];
    const float* cw = (const float*)d_in[5];
    const float* cb = (const float*)d_in[6];
    const float* gamma = (const float*)d_in[7];
    const float* beta = (const float*)d_in[8];
    float* out = (float*)d_out;

    static int smem_set = 0;
    if (!smem_set) {
        cudaFuncSetAttribute(k_mma, cudaFuncAttributeMaxDynamicSharedMemorySize,
                             SMEM_FLOATS * 4);
        smem_set = 1;
    }

    k_prep1<<<16, 256>>>(Wr, Wi);
    k_prep2<<<16, 256>>>(br, bi);
    k_mma<<<1024, 256, SMEM_FLOATS * 4>>>(x);
    k_fused<<<512, 256>>>(cw, cb, gamma, beta, out);
}

// round 15
// speedup vs baseline: 1.1044x; 1.0218x over previous
#include <cuda_runtime.h>

#define BATCH 8
#define HH 2048
#define WW 2048
#define DD 16
#define FEAT 256
#define NPIX (128 * 128)

typedef unsigned long long ull;
typedef unsigned int uint;

// ---------------- device scratch ----------------
__device__ float g_tc[256];
__device__ float g_ts[256];
__device__ float g_R[DD][FEAT];
__device__ float g_I[DD][FEAT];
__device__ float g_c[DD];
__device__ float g_Bhi[4096];        // B fragments (tf32 hi), lane-packed
__device__ float g_Blo[4096];        // B fragments (tf32 lo), lane-packed
__device__ float g_img[BATCH * DD * NPIX];   // 8 MB [b][d][i][j]
__device__ float g_ps[512];
__device__ float g_pq[512];
__device__ int g_cnt[DD];

// ---------------- helpers ----------------
__device__ __forceinline__ uint tf32r(float a) {
    uint u; asm("cvt.rna.tf32.f32 %0, %1;" : "=r"(u) : "f"(a)); return u;
}
__device__ __forceinline__ void cpasync16(uint saddr, const void* gaddr) {
    asm volatile("cp.async.cg.shared.global [%0], [%1], 16;" :: "r"(saddr), "l"(gaddr));
}
__device__ __forceinline__ int ld_acq(const int* p) {
    int v; asm volatile("ld.acquire.gpu.b32 %0, [%1];" : "=r"(v) : "l"(p)); return v;
}
__device__ __forceinline__ void mma_tf32(float* c, const uint* a, uint b0, uint b1) {
    asm volatile(
        "mma.sync.aligned.m16n8k8.row.col.f32.tf32.tf32.f32 "
        "{%0,%1,%2,%3}, {%4,%5,%6,%7}, {%8,%9}, {%0,%1,%2,%3};"
        : "+f"(c[0]), "+f"(c[1]), "+f"(c[2]), "+f"(c[3])
        : "r"(a[0]), "r"(a[1]), "r"(a[2]), "r"(a[3]), "r"(b0), "r"(b1));
}

// ---------------- K1: table + R[j,f], I[j,f] ----------------
__global__ void k_prep1(const float* __restrict__ Wr, const float* __restrict__ Wi) {
    __shared__ float sc[256], ss[256], wr[256], wi[256];
    int f = threadIdx.x, j = blockIdx.x;
    float s, c;
    sincospif((float)f * (1.0f / 128.0f), &s, &c);
    sc[f] = c; ss[f] = s;
    if (j == 0) { g_tc[f] = c; g_ts[f] = s; }
    wr[f] = Wr[j * FEAT + f]; wi[f] = Wi[j * FEAT + f];
    __syncthreads();
    float R = 0.f, I = 0.f;
    for (int d = 0; d < 256; ++d) {
        int t = (d * f) & 255;
        float cc = sc[t], s2 = ss[t];
        R += wr[d] * cc + wi[d] * s2;
        I += wi[d] * cc - wr[d] * s2;
    }
    g_R[j][f] = R; g_I[j][f] = I;
}

// ---------------- K2: M^T -> B fragments directly; c[k]; reset counters ------
__global__ void k_prep2(const float* __restrict__ br, const float* __restrict__ bi) {
    int e = blockIdx.x * 256 + threadIdx.x;
    int f = e >> 4, n = e & 15;
    float m = 0.f;
    for (int j = 0; j < DD; ++j) {
        int t = (16 * j * n) & 255;
        m += g_R[j][f] * g_tc[t] - g_I[j][f] * g_ts[t];
    }
    m *= (1.0f / 16.0f);
    uint hb = tf32r(m);
    float hi = __uint_as_float(hb);
    uint lb = tf32r(m - hi);
    int ks = f >> 3, rem = f & 7;
    int jj = rem >> 2;
    int lane = ((n & 7) << 2) | (rem & 3);
    int nt = n >> 3;
    int idx = (ks << 7) | (nt << 6) | (lane << 1) | jj;
    g_Bhi[idx] = hi;
    g_Blo[idx] = __uint_as_float(lb);
    if (e < DD) {
        float cc = 0.f;
        for (int j = 0; j < DD; ++j) {
            int t = (16 * j * e) & 255;
            cc += (br[j] - bi[j]) * g_tc[t] - (br[j] + bi[j]) * g_ts[t];
        }
        g_c[e] = cc * (1.0f / 16.0f);
        g_cnt[e] = 0;
    }
}

// ---------------- K3: tensor-core patch GEMM, per-warp decoupled pipeline -----
// Block = one (b, ph), 256 threads / 8 warps. Warp w owns m16 tile w
// (patches w*16..w*16+15) and stages ONLY its 1KB row-slice via cp.async into
// a private 2-buffer ring (wait_group + syncwarp, no block barriers in loop).
// B block-shared (one barrier before the mainloop).
// 3-term tf32 compensation: ah*bh + al*bh + ah*bl.
#define AWARP 640            // floats per warp (2 buffers x 320)
#define SB_BHI (8 * AWARP)   // 5120 floats
#define SB_BLO (SB_BHI + 4096)
#define SMEM_FLOATS (SB_BLO + 4096)

__global__ void __launch_bounds__(256, 4) k_mma(const float* __restrict__ x) {
    extern __shared__ float shm[];
    uint sb = (uint)__cvta_generic_to_shared(shm);
    int tid = threadIdx.x, w = tid >> 5, lane = tid & 31;
    int r = lane >> 2, pr = lane & 3;
    int blk = blockIdx.x;
    int b = blk >> 7, ph = blk & 127;

    const char* xbase = (const char*)(x + ((size_t)b * HH + (size_t)ph * 16) * WW)
                        + w * 1024;             // this warp's column slice
    uint awbase = sb + (uint)(w * AWARP) * 4;   // this warp's A ring (bytes)

    // chunk mapping for this lane: k in {lane, lane+32}, k = p*4 + c4
    int k0c = lane, k1c = lane + 32;
    uint d0 = (uint)((k0c >> 2) * 80 + (k0c & 3) * 16);
    uint d1 = (uint)((k1c >> 2) * 80 + (k1c & 3) * 16);

    // g0: B (16KB hi + 16KB lo)
#pragma unroll
    for (int i = 0; i < 4; ++i) {
        int cid = tid + i * 256;
        cpasync16(sb + (uint)(SB_BHI * 4) + (uint)cid * 16, (const char*)g_Bhi + cid * 16);
        cpasync16(sb + (uint)(SB_BLO * 4) + (uint)cid * 16, (const char*)g_Blo + cid * 16);
    }
    asm volatile("cp.async.commit_group;");
    // g1: A row 0, g2: A row 1 (per-warp slices)
#pragma unroll
    for (int st = 0; st < 2; ++st) {
        const char* src = xbase + (size_t)st * (WW * 4);
        uint dbase = awbase + (uint)(st * 320) * 4;
        cpasync16(dbase + d0, src + (size_t)k0c * 16);
        cpasync16(dbase + d1, src + (size_t)k1c * 16);
        asm volatile("cp.async.commit_group;");
    }

    // one-time: B visible to all warps
    asm volatile("cp.async.wait_group 2;");
    __syncthreads();

    float acc[2][4];
#pragma unroll
    for (int nt = 0; nt < 2; ++nt)
#pragma unroll
        for (int i = 0; i < 4; ++i) acc[nt][i] = 0.f;

    int afrag = r * 20 + pr;   // fragment base (floats) within warp buffer

#pragma unroll 1
    for (int s1 = 0; s1 < 16; ++s1) {
        asm volatile("cp.async.wait_group 1;");   // row s1 resident
        __syncwarp();
        const float* Aw = shm + w * AWARP + (s1 & 1) * 320 + afrag;
        const float2* Bp = (const float2*)(shm + SB_BHI) + s1 * 128 + lane;
        const float2* Lp = (const float2*)(shm + SB_BLO) + s1 * 128 + lane;
#pragma unroll
        for (int kh = 0; kh < 2; ++kh) {
            float2 bh0 = Bp[kh * 64];
            float2 bh1 = Bp[kh * 64 + 32];
            float2 bl0 = Lp[kh * 64];
            float2 bl1 = Lp[kh * 64 + 32];
            uint bh0x = __float_as_uint(bh0.x), bh0y = __float_as_uint(bh0.y);
            uint bh1x = __float_as_uint(bh1.x), bh1y = __float_as_uint(bh1.y);
            uint bl0x = __float_as_uint(bl0.x), bl0y = __float_as_uint(bl0.y);
            uint bl1x = __float_as_uint(bl1.x), bl1y = __float_as_uint(bl1.y);
            const float* Ak = Aw + kh * 8;
            float a0 = Ak[0], a2 = Ak[4];
            float a1 = Ak[160], a3 = Ak[164];
            uint ah[4], al[4];
            ah[0] = tf32r(a0); al[0] = tf32r(a0 - __uint_as_float(ah[0]));
            ah[1] = tf32r(a1); al[1] = tf32r(a1 - __uint_as_float(ah[1]));
            ah[2] = tf32r(a2); al[2] = tf32r(a2 - __uint_as_float(ah[2]));
            ah[3] = tf32r(a3); al[3] = tf32r(a3 - __uint_as_float(ah[3]));
            mma_tf32(acc[0], ah, bh0x, bh0y);
            mma_tf32(acc[0], al, bh0x, bh0y);
            mma_tf32(acc[0], ah, bl0x, bl0y);
            mma_tf32(acc[1], ah, bh1x, bh1y);
            mma_tf32(acc[1], al, bh1x, bh1y);
            mma_tf32(acc[1], ah, bl1x, bl1y);
        }
        __syncwarp();                       // all lanes done reading buffer
        if (s1 < 14) {                      // stage row s1+2 into buffer (s1&1)
            const char* src = xbase + (size_t)(s1 + 2) * (WW * 4);
            uint dbase = awbase + (uint)((s1 & 1) * 320) * 4;
            cpasync16(dbase + d0, src + (size_t)k0c * 16);
            cpasync16(dbase + d1, src + (size_t)k1c * 16);
        }
        asm volatile("cp.async.commit_group;");
    }

    // epilogue: add c[n], scatter to g_img [b][n][ph*128 + p]
    float cn[2][2];
#pragma unroll
    for (int nt = 0; nt < 2; ++nt)
#pragma unroll
        for (int j = 0; j < 2; ++j) cn[nt][j] = g_c[nt * 8 + pr * 2 + j];

    float* gb = g_img + (size_t)b * DD * NPIX + ph * 128;
    int p0 = w * 16 + r;
#pragma unroll
    for (int nt = 0; nt < 2; ++nt) {
        int n0 = nt * 8 + pr * 2;
        gb[(size_t)n0 * NPIX + p0] = acc[nt][0] + cn[nt][0];
        gb[(size_t)(n0 + 1) * NPIX + p0] = acc[nt][1] + cn[nt][1];
        gb[(size_t)n0 * NPIX + p0 + 8] = acc[nt][2] + cn[nt][0];
        gb[(size_t)(n0 + 1) * NPIX + p0 + 8] = acc[nt][3] + cn[nt][1];
    }
}

// ---------------- float4 + shfl rolling 3x3 conv ----------------
__device__ __forceinline__ void conv_rows(float4 v, int lane, const float* w,
                                          float4& h0, float4& h1, float4& h2) {
    float l = __shfl_up_sync(0xffffffffu, v.w, 1);
    float rr = __shfl_down_sync(0xffffffffu, v.x, 1);
    if (lane == 0) l = 0.f;
    if (lane == 31) rr = 0.f;
    float lx = l, ly = v.x, lz = v.y, lw = v.z;
    float rx = v.y, ry = v.z, rz = v.w, rw = rr;
#define HROW(H, W0, W1, W2)                                   \
    H.x = W0 * lx + W1 * v.x + W2 * rx;                       \
    H.y = W0 * ly + W1 * v.y + W2 * ry;                       \
    H.z = W0 * lz + W1 * v.z + W2 * rz;                       \
    H.w = W0 * lw + W1 * v.w + W2 * rw;
    HROW(h0, w[0], w[1], w[2])
    HROW(h1, w[3], w[4], w[5])
    HROW(h2, w[6], w[7], w[8])
#undef HROW
}

__device__ __forceinline__ float4 ld_row(const float* __restrict__ base, int r, int lane) {
    if ((unsigned)r < 128u) return ((const float4*)(base + r * 128))[lane];
    return make_float4(0.f, 0.f, 0.f, 0.f);
}

// ---------------- K4: fused conv + stats + grid-sync + BN + write -------------
__global__ void __launch_bounds__(256) k_fused(const float* __restrict__ cw,
                                               const float* __restrict__ cb,
                                               const float* __restrict__ gamma,
                                               const float* __restrict__ beta,
                                               float* __restrict__ out) {
    int blk = blockIdx.x;            // bd*4 + slice
    int bd = blk >> 2;
    int d = bd & 15;
    int slice = blk & 3;
    int tid = threadIdx.x;
    int lane = tid & 31, wp = tid >> 5;
    int r0 = slice * 32 + wp * 4;
    float w[9];
#pragma unroll
    for (int t = 0; t < 9; ++t) w[t] = cw[d * 9 + t];
    float bias = cb[d];
    const float* base = g_img + (size_t)bd * NPIX;

    float4 A = make_float4(0, 0, 0, 0), B = make_float4(0, 0, 0, 0);
    float4 cv[4];
    float s = 0.f, sq = 0.f;
#pragma unroll
    for (int r = r0 - 1; r <= r0 + 4; ++r) {
        float4 v = ld_row(base, r, lane);
        float4 h0, h1, h2;
        conv_rows(v, lane, w, h0, h1, h2);
        if (r >= r0 + 1) {
            float4 o;
            o.x = A.x + h2.x + bias;
            o.y = A.y + h2.y + bias;
            o.z = A.z + h2.z + bias;
            o.w = A.w + h2.w + bias;
            cv[r - 1 - r0] = o;
            s += o.x + o.y + o.z + o.w;
            sq += o.x * o.x + o.y * o.y + o.z * o.z + o.w * o.w;
        }
        A.x = B.x + h1.x; A.y = B.y + h1.y; A.z = B.z + h1.z; A.w = B.w + h1.w;
        B = h0;
    }
#pragma unroll
    for (int off = 16; off; off >>= 1) {
        s += __shfl_down_sync(0xffffffffu, s, off);
        sq += __shfl_down_sync(0xffffffffu, sq, off);
    }
    __shared__ float rs[8], rq[8];
    if (lane == 0) { rs[wp] = s; rq[wp] = sq; }
    __syncthreads();
    if (tid == 0) {
        float ts = 0.f, tq = 0.f;
#pragma unroll
        for (int i = 0; i < 8; ++i) { ts += rs[i]; tq += rq[i]; }
        g_ps[blk] = ts;
        g_pq[blk] = tq;
        __threadfence();
        atomicAdd(&g_cnt[d], 1);
        while (ld_acq(&g_cnt[d]) < 32) {}
    }
    __syncthreads();

    __shared__ float sp[32], sq2[32];
    __shared__ float smu, ssc;
    if (tid < 32) {
        int bb = tid >> 2, sl = tid & 3;
        int idx = ((bb * DD + d) << 2) + sl;
        sp[tid] = __ldcg(&g_ps[idx]);
        sq2[tid] = __ldcg(&g_pq[idx]);
        __syncwarp();
        if (tid == 0) {
            float S = 0.f, Q = 0.f;
#pragma unroll
            for (int i = 0; i < 32; ++i) { S += sp[i]; Q += sq2[i]; }
            float n = 131072.0f;
            float mu = S / n;
            float var = Q / n - mu * mu;
            smu = mu;
            ssc = rsqrtf(var + 1e-5f) * gamma[d];
        }
    }
    __syncthreads();
    float mu = smu, sc = ssc, bt = beta[d];

    float4* op = (float4*)(out + (size_t)bd * NPIX) + lane;
#pragma unroll
    for (int ri = 0; ri < 4; ++ri) {
        float4 o;
        o.x = (cv[ri].x - mu) * sc + bt;
        o.y = (cv[ri].y - mu) * sc + bt;
        o.z = (cv[ri].z - mu) * sc + bt;
        o.w = (cv[ri].w - mu) * sc + bt;
        op[(r0 + ri) * 32] = o;
    }
}

extern "C" void kernel_launch(void* const* d_in, const int* in_sizes, int n_in,
                              void* d_out, int out_size) {
    const float* x = (const float*)d_in[0];
    const float* Wr = (const float*)d_in[1];
    const float* br = (const float*)d_in[2];
    const float* Wi = (const float*)d_in[3];
    const float* bi = (const float*)d_in[4];
    const float* cw = (const float*)d_in[5];
    const float* cb = (const float*)d_in[6];
    const float* gamma = (const float*)d_in[7];
    const float* beta = (const float*)d_in[8];
    float* out = (float*)d_out;

    static int smem_set = 0;
    if (!smem_set) {
        cudaFuncSetAttribute(k_mma, cudaFuncAttributeMaxDynamicSharedMemorySize,
                             SMEM_FLOATS * 4);
        smem_set = 1;
    }

    k_prep1<<<16, 256>>>(Wr, Wi);
    k_prep2<<<16, 256>>>(br, bi);
    k_mma<<<1024, 256, SMEM_FLOATS * 4>>>(x);
    k_fused<<<512, 256>>>(cw, cb, gamma, beta, out);
}